// round 4
// baseline (speedup 1.0000x reference)
#include <cuda_runtime.h>
#include <math.h>
#include <stdint.h>

// ---------------------------------------------------------------------------
// MultiviewDecoderBlock (Vx=8, Vy=8, B=4, N=196, C=768, H=12, DH=64, M=4)
// TF32 tensor-core GEMMs + TF32 tensor-core attention. Graph-capturable.
// ---------------------------------------------------------------------------

constexpr int VX = 8, BB = 4, NN = 196, CC = 768, HH = 12, DHH = 64, MV = 4;
constexpr int HID = 4 * CC;            // 3072
constexpr int VB = VX * BB;            // 32
constexpr int T  = VB * NN;            // 6272 tokens (x)
constexpr int TT = VX * MV * BB * NN;  // 25088 tokens (cross out)
constexpr int PSELF  = VB * HH;            // 384
constexpr int PCROSS = VX * MV * BB * HH;  // 1536
constexpr float ATTN_SCALE = 0.125f;       // 64^-0.5

// -------------------------- device scratch ---------------------------------
__device__ float g_x  [T * CC];
__device__ float g_h  [T * CC];
__device__ float g_yn [T * CC];
__device__ float g_qkv[T * 3 * CC];
__device__ float g_q  [T * CC];
__device__ float g_k  [T * CC];
__device__ float g_v  [T * CC];
__device__ float g_o  [T * CC];
__device__ float g_big [TT * CC];
__device__ float g_big2[TT * CC];

extern __shared__ __align__(16) unsigned char dyn_smem[];

// ----------------------------- utility -------------------------------------
__global__ void copy_kernel(const float* __restrict__ src, float* __restrict__ dst, int n) {
    int i = blockIdx.x * blockDim.x + threadIdx.x;
    if (i < n) dst[i] = src[i];
}

__global__ void layernorm_kernel(const float* __restrict__ in,
                                 const float* __restrict__ w,
                                 const float* __restrict__ b,
                                 float* __restrict__ out) {
    int row = blockIdx.x;
    const float* xr = in + (size_t)row * CC;
    float* orow = out + (size_t)row * CC;
    int tid = threadIdx.x;
    float v0 = xr[tid], v1 = xr[tid + 256], v2 = xr[tid + 512];
    float s  = v0 + v1 + v2;
    float sq = v0 * v0 + v1 * v1 + v2 * v2;
    #pragma unroll
    for (int off = 16; off; off >>= 1) {
        s  += __shfl_xor_sync(0xffffffffu, s, off);
        sq += __shfl_xor_sync(0xffffffffu, sq, off);
    }
    __shared__ float red[2][8];
    int warp = tid >> 5, lane = tid & 31;
    if (lane == 0) { red[0][warp] = s; red[1][warp] = sq; }
    __syncthreads();
    float ts = 0.f, tsq = 0.f;
    #pragma unroll
    for (int i = 0; i < 8; i++) { ts += red[0][i]; tsq += red[1][i]; }
    float mu = ts * (1.0f / CC);
    float var = tsq * (1.0f / CC) - mu * mu;
    float rstd = rsqrtf(var + 1e-5f);
    orow[tid]       = (v0 - mu) * rstd * w[tid]       + b[tid];
    orow[tid + 256] = (v1 - mu) * rstd * w[tid + 256] + b[tid + 256];
    orow[tid + 512] = (v2 - mu) * rstd * w[tid + 512] + b[tid + 512];
}

__global__ void merge_kernel(const float* __restrict__ proj, float* __restrict__ x) {
    int idx = blockIdx.x * blockDim.x + threadIdx.x;
    if (idx >= T * CC) return;
    int c = idx % CC;
    int n = (idx / CC) % NN;
    int b = (idx / (CC * NN)) % BB;
    int v = idx / (CC * NN * BB);
    size_t base = ((((size_t)v * MV) * BB + b) * NN + n) * CC + c;
    size_t ms = (size_t)BB * NN * CC;
    float mx = proj[base];
    #pragma unroll
    for (int m = 1; m < MV; m++) mx = fmaxf(mx, proj[base + (size_t)m * ms]);
    x[idx] += mx;
}

// ----------------------------- tf32 helpers ---------------------------------
__device__ __forceinline__ unsigned f2tf(float f) {
    unsigned u;
    asm("cvt.rna.tf32.f32 %0, %1;" : "=r"(u) : "f"(f));
    return u;
}

__device__ __forceinline__ void mma8(float* c, const unsigned* a, const unsigned* b) {
    asm volatile(
        "mma.sync.aligned.m16n8k8.row.col.f32.tf32.tf32.f32 "
        "{%0,%1,%2,%3},{%4,%5,%6,%7},{%8,%9},{%0,%1,%2,%3};\n"
        : "+f"(c[0]), "+f"(c[1]), "+f"(c[2]), "+f"(c[3])
        : "r"(a[0]), "r"(a[1]), "r"(a[2]), "r"(a[3]), "r"(b[0]), "r"(b[1]));
}

// --------------------- TF32 tensor GEMM: C = A @ B^T ------------------------
constexpr int GEMM_SMEM = 2 * 128 * 32 * 4 * 2;  // 65536 bytes

template<int EPI>
__global__ void __launch_bounds__(256) gemm_tf32(
    const float* __restrict__ A, const float* __restrict__ Bw,
    const float* __restrict__ bias, const float* __restrict__ res,
    float* __restrict__ C, int Mdim, int Ndim, int Kdim)
{
    unsigned* As = (unsigned*)dyn_smem;             // [2][128][32]
    unsigned* Bs = As + 2 * 128 * 32;

    const int tid = threadIdx.x;
    const int lane = tid & 31, warp = tid >> 5;
    const int wm = (warp >> 2) * 64;
    const int wn = (warp & 3) * 32;
    const int bm = blockIdx.y * 128, bn = blockIdx.x * 128;
    const int lr = tid >> 3;
    const int lk = (tid & 7) * 4;
    const float* Ag = A  + (size_t)(bm + lr) * Kdim + lk;
    const float* Bg = Bw + (size_t)(bn + lr) * Kdim + lk;

    float acc[4][4][4];
    #pragma unroll
    for (int i = 0; i < 4; i++)
        #pragma unroll
        for (int j = 0; j < 4; j++)
            #pragma unroll
            for (int t = 0; t < 4; t++) acc[i][j][t] = 0.f;

    float4 pa[4], pb[4];
    #pragma unroll
    for (int i = 0; i < 4; i++) {
        pa[i] = *(const float4*)(Ag + (size_t)(32 * i) * Kdim);
        pb[i] = *(const float4*)(Bg + (size_t)(32 * i) * Kdim);
    }
    {
        #pragma unroll
        for (int i = 0; i < 4; i++) {
            int row = lr + 32 * i;
            int g = (lk >> 2) ^ (row & 7);
            uint4 av, bv;
            av.x = f2tf(pa[i].x); av.y = f2tf(pa[i].y); av.z = f2tf(pa[i].z); av.w = f2tf(pa[i].w);
            bv.x = f2tf(pb[i].x); bv.y = f2tf(pb[i].y); bv.z = f2tf(pb[i].z); bv.w = f2tf(pb[i].w);
            *(uint4*)(As + row * 32 + g * 4) = av;
            *(uint4*)(Bs + row * 32 + g * 4) = bv;
        }
    }
    __syncthreads();

    const int r = lane >> 2, kq = lane & 3;
    const int nk = Kdim >> 5;
    for (int kt = 0; kt < nk; kt++) {
        const int buf = kt & 1;
        if (kt + 1 < nk) {
            const float* Ag2 = Ag + (kt + 1) * 32;
            const float* Bg2 = Bg + (kt + 1) * 32;
            #pragma unroll
            for (int i = 0; i < 4; i++) {
                pa[i] = *(const float4*)(Ag2 + (size_t)(32 * i) * Kdim);
                pb[i] = *(const float4*)(Bg2 + (size_t)(32 * i) * Kdim);
            }
        }
        {
            const unsigned* Ab = As + buf * 4096;
            const unsigned* Bb = Bs + buf * 4096;
            #pragma unroll
            for (int ks = 0; ks < 4; ks++) {
                const int g0 = (((2 * ks)     ^ r) << 2) + kq;
                const int g1 = (((2 * ks + 1) ^ r) << 2) + kq;
                unsigned a[4][4], b[4][2];
                #pragma unroll
                for (int mf = 0; mf < 4; mf++) {
                    const unsigned* p = Ab + (wm + mf * 16 + r) * 32;
                    a[mf][0] = p[g0];
                    a[mf][1] = p[8 * 32 + g0];
                    a[mf][2] = p[g1];
                    a[mf][3] = p[8 * 32 + g1];
                }
                #pragma unroll
                for (int nf = 0; nf < 4; nf++) {
                    const unsigned* p = Bb + (wn + nf * 8 + r) * 32;
                    b[nf][0] = p[g0];
                    b[nf][1] = p[g1];
                }
                #pragma unroll
                for (int mf = 0; mf < 4; mf++)
                    #pragma unroll
                    for (int nf = 0; nf < 4; nf++)
                        mma8(acc[mf][nf], a[mf], b[nf]);
            }
        }
        if (kt + 1 < nk) {
            unsigned* Ad = As + (buf ^ 1) * 4096;
            unsigned* Bd = Bs + (buf ^ 1) * 4096;
            #pragma unroll
            for (int i = 0; i < 4; i++) {
                int row = lr + 32 * i;
                int g = (lk >> 2) ^ (row & 7);
                uint4 av, bv;
                av.x = f2tf(pa[i].x); av.y = f2tf(pa[i].y); av.z = f2tf(pa[i].z); av.w = f2tf(pa[i].w);
                bv.x = f2tf(pb[i].x); bv.y = f2tf(pb[i].y); bv.z = f2tf(pb[i].z); bv.w = f2tf(pb[i].w);
                *(uint4*)(Ad + row * 32 + g * 4) = av;
                *(uint4*)(Bd + row * 32 + g * 4) = bv;
            }
        }
        __syncthreads();
    }

    #pragma unroll
    for (int mf = 0; mf < 4; mf++) {
        #pragma unroll
        for (int nf = 0; nf < 4; nf++) {
            const int col = bn + wn + nf * 8 + (lane & 3) * 2;
            float bb0 = 0.f, bb1 = 0.f;
            if (EPI >= 1) { bb0 = bias[col]; bb1 = bias[col + 1]; }
            #pragma unroll
            for (int hh = 0; hh < 2; hh++) {
                const size_t row = (size_t)(bm + wm + mf * 16 + (lane >> 2) + hh * 8);
                float v0 = acc[mf][nf][hh * 2 + 0] + bb0;
                float v1 = acc[mf][nf][hh * 2 + 1] + bb1;
                if (EPI == 2) {
                    v0 += res[row * Ndim + col];
                    v1 += res[row * Ndim + col + 1];
                }
                if (EPI == 3) {
                    v0 = 0.5f * v0 * (1.0f + erff(v0 * 0.70710678118654752f));
                    v1 = 0.5f * v1 * (1.0f + erff(v1 * 0.70710678118654752f));
                }
                *(float2*)(C + row * Ndim + col) = make_float2(v0, v1);
            }
        }
    }
}

// ------------------- TF32 mma attention ---------------------------------
// One block: one head-problem p, 64 query rows. 256 threads = 8 warps:
// warp = wn*4 + wm; wm selects 16 query rows, wn selects 104-key half.
// Keys padded to 208 (26 tiles of 8). Scores fully materialized in regs.
constexpr int KP   = 208;   // padded key count
constexpr int NTJ  = 13;    // score n-tiles per warp (104 keys)
constexpr int KST  = 68;    // Q/K/V smem stride (floats)
constexpr int PST  = 212;   // P smem stride (floats)
constexpr int OFF_Q = 0;                       // 64*68   = 4352
constexpr int OFF_K = 64 * KST;                // 4352
constexpr int OFF_V = OFF_K + KP * KST;        // 18496
constexpr int OFF_RED = OFF_V + KP * KST;      // 32640 : redmax[2][64], redsum[2][64]
constexpr int ATTN_SMEM = (OFF_RED + 256) * 4; // 131584 bytes

template<bool CROSS>
__global__ void __launch_bounds__(256) attn_mma(
    const float* __restrict__ Qsrc, const float* __restrict__ Ksrc,
    const float* __restrict__ Vsrc, const int* __restrict__ rel,
    float* __restrict__ Out)
{
    float* smem = (float*)dyn_smem;
    float* Qs = smem + OFF_Q;
    float* Ks = smem + OFF_K;
    float* Vs = smem + OFF_V;
    float* Ps = smem;           // overlaps Q+K after scores are in regs
    float* redmax = smem + OFF_RED;        // [2][64]
    float* redsum = smem + OFF_RED + 128;  // [2][64]

    const int p = blockIdx.y;
    const int m0 = blockIdx.x * 64;
    const int tid = threadIdx.x;
    const int lane = tid & 31, warp = tid >> 5;
    const int wm = warp & 3, wn = warp >> 2;
    const int r = lane >> 2, q = lane & 3;

    const float *qp, *kp, *vp;
    float* op;
    int qrs, kvs;
    if (!CROSS) {
        int vb = p / HH, h2 = p % HH;
        const float* base = Qsrc + (size_t)vb * NN * 3 * CC;
        qp = base + h2 * DHH;
        kp = base + CC + h2 * DHH;
        vp = base + 2 * CC + h2 * DHH;
        qrs = 3 * CC; kvs = 3 * CC;
        op = Out + (size_t)vb * NN * CC + h2 * DHH;
    } else {
        int h2 = p % HH; int rr = p / HH;
        int b = rr % BB; int r2 = rr / BB;
        int mvi = r2 % MV; int v = r2 / MV;
        int vy = rel[v * MV + mvi];
        qp = Qsrc + ((size_t)(v * BB + b) * NN) * CC + h2 * DHH; qrs = CC;
        kp = Ksrc + ((size_t)(vy * BB + b) * NN) * CC + h2 * DHH;
        vp = Vsrc + ((size_t)(vy * BB + b) * NN) * CC + h2 * DHH; kvs = CC;
        op = Out + (size_t)rr * NN * CC + h2 * DHH;
    }

    // ---- load Q (64 x 64), tf32-converted ----
    #pragma unroll
    for (int it = 0; it < 4; it++) {
        int idx = tid + 256 * it;
        int row = idx >> 4, c4 = (idx & 15) * 4;
        float4 qv = make_float4(0.f, 0.f, 0.f, 0.f);
        if (m0 + row < NN) qv = *(const float4*)(qp + (size_t)(m0 + row) * qrs + c4);
        unsigned* d = (unsigned*)&Qs[row * KST + c4];
        d[0] = f2tf(qv.x); d[1] = f2tf(qv.y); d[2] = f2tf(qv.z); d[3] = f2tf(qv.w);
    }
    // ---- load K, V (208 x 64), zero-padded rows >= 196 ----
    #pragma unroll
    for (int it = 0; it < 13; it++) {
        int idx = tid + 256 * it;
        int row = idx >> 4, c4 = (idx & 15) * 4;
        float4 kv = make_float4(0.f, 0.f, 0.f, 0.f);
        float4 vv = make_float4(0.f, 0.f, 0.f, 0.f);
        if (row < NN) {
            kv = *(const float4*)(kp + (size_t)row * kvs + c4);
            vv = *(const float4*)(vp + (size_t)row * kvs + c4);
        }
        unsigned* dk = (unsigned*)&Ks[row * KST + c4];
        dk[0] = f2tf(kv.x); dk[1] = f2tf(kv.y); dk[2] = f2tf(kv.z); dk[3] = f2tf(kv.w);
        unsigned* dv = (unsigned*)&Vs[row * KST + c4];
        dv[0] = f2tf(vv.x); dv[1] = f2tf(vv.y); dv[2] = f2tf(vv.z); dv[3] = f2tf(vv.w);
    }
    __syncthreads();

    // ---- scores: warp computes m16 x n104 over k=64 ----
    const int n0 = wn * (NTJ * 8);
    float sc[NTJ][4];
    #pragma unroll
    for (int j = 0; j < NTJ; j++)
        #pragma unroll
        for (int t = 0; t < 4; t++) sc[j][t] = 0.f;

    const unsigned* Qu = (const unsigned*)Qs;
    const unsigned* Ku = (const unsigned*)Ks;
    const unsigned* Vu = (const unsigned*)Vs;

    #pragma unroll
    for (int kt = 0; kt < 8; kt++) {
        unsigned a[4];
        const unsigned* ap = Qu + (wm * 16 + r) * KST + kt * 8 + q;
        a[0] = ap[0];
        a[1] = ap[8 * KST];
        a[2] = ap[4];
        a[3] = ap[8 * KST + 4];
        #pragma unroll
        for (int j = 0; j < NTJ; j++) {
            unsigned b[2];
            const unsigned* bp = Ku + (n0 + j * 8 + r) * KST + kt * 8 + q;
            b[0] = bp[0];
            b[1] = bp[4];
            mma8(sc[j], a, b);
        }
    }

    // ---- scale + mask ----
    #pragma unroll
    for (int j = 0; j < NTJ; j++) {
        int cbase = n0 + j * 8 + 2 * q;
        #pragma unroll
        for (int t = 0; t < 4; t++) {
            int col = cbase + (t & 1);
            sc[j][t] = (col < NN) ? sc[j][t] * ATTN_SCALE : -1e30f;
        }
    }

    // ---- row max (half), cross-half via smem ----
    float mx0 = -1e30f, mx1 = -1e30f;
    #pragma unroll
    for (int j = 0; j < NTJ; j++) {
        mx0 = fmaxf(mx0, fmaxf(sc[j][0], sc[j][1]));
        mx1 = fmaxf(mx1, fmaxf(sc[j][2], sc[j][3]));
    }
    mx0 = fmaxf(mx0, __shfl_xor_sync(0xffffffffu, mx0, 1));
    mx0 = fmaxf(mx0, __shfl_xor_sync(0xffffffffu, mx0, 2));
    mx1 = fmaxf(mx1, __shfl_xor_sync(0xffffffffu, mx1, 1));
    mx1 = fmaxf(mx1, __shfl_xor_sync(0xffffffffu, mx1, 2));
    int rowl = wm * 16 + r;
    if (q == 0) {
        redmax[wn * 64 + rowl] = mx0;
        redmax[wn * 64 + rowl + 8] = mx1;
    }
    __syncthreads();   // also: all K/Q reads done -> Ps region reusable
    float fm0 = fmaxf(redmax[rowl], redmax[64 + rowl]);
    float fm1 = fmaxf(redmax[rowl + 8], redmax[64 + rowl + 8]);

    // ---- exp, row sum, write P (tf32) ----
    float s0 = 0.f, s1 = 0.f;
    #pragma unroll
    for (int j = 0; j < NTJ; j++) {
        sc[j][0] = __expf(sc[j][0] - fm0);
        sc[j][1] = __expf(sc[j][1] - fm0);
        sc[j][2] = __expf(sc[j][2] - fm1);
        sc[j][3] = __expf(sc[j][3] - fm1);
        s0 += sc[j][0] + sc[j][1];
        s1 += sc[j][2] + sc[j][3];
    }
    s0 += __shfl_xor_sync(0xffffffffu, s0, 1);
    s0 += __shfl_xor_sync(0xffffffffu, s0, 2);
    s1 += __shfl_xor_sync(0xffffffffu, s1, 1);
    s1 += __shfl_xor_sync(0xffffffffu, s1, 2);
    if (q == 0) {
        redsum[wn * 64 + rowl] = s0;
        redsum[wn * 64 + rowl + 8] = s1;
    }
    #pragma unroll
    for (int j = 0; j < NTJ; j++) {
        int cbase = n0 + j * 8 + 2 * q;
        unsigned* p0 = (unsigned*)&Ps[rowl * PST + cbase];
        unsigned* p1 = (unsigned*)&Ps[(rowl + 8) * PST + cbase];
        p0[0] = f2tf(sc[j][0]); p0[1] = f2tf(sc[j][1]);
        p1[0] = f2tf(sc[j][2]); p1[1] = f2tf(sc[j][3]);
    }
    __syncthreads();

    // ---- O = P @ V : warp computes m16 x n32 over k=208 ----
    const int oc0 = wn * 32;
    float oacc[4][4];
    #pragma unroll
    for (int j = 0; j < 4; j++)
        #pragma unroll
        for (int t = 0; t < 4; t++) oacc[j][t] = 0.f;

    const unsigned* Pu = (const unsigned*)Ps;
    #pragma unroll 2
    for (int kt = 0; kt < KP / 8; kt++) {
        unsigned a[4];
        const unsigned* ap = Pu + (wm * 16 + r) * PST + kt * 8 + q;
        a[0] = ap[0];
        a[1] = ap[8 * PST];
        a[2] = ap[4];
        a[3] = ap[8 * PST + 4];
        #pragma unroll
        for (int j = 0; j < 4; j++) {
            unsigned b[2];
            const unsigned* bp = Vu + (kt * 8 + q) * KST + oc0 + j * 8 + r;
            b[0] = bp[0];
            b[1] = bp[4 * KST];
            mma8(oacc[j], a, b);
        }
    }

    // ---- store O, scaled by 1/rowsum ----
    float inv0 = 1.0f / (redsum[rowl] + redsum[64 + rowl]);
    float inv1 = 1.0f / (redsum[rowl + 8] + redsum[64 + rowl + 8]);
    int mg0 = m0 + rowl, mg1 = m0 + rowl + 8;
    #pragma unroll
    for (int j = 0; j < 4; j++) {
        int col = oc0 + j * 8 + 2 * q;
        if (mg0 < NN)
            *(float2*)(op + (size_t)mg0 * CC + col) =
                make_float2(oacc[j][0] * inv0, oacc[j][1] * inv0);
        if (mg1 < NN)
            *(float2*)(op + (size_t)mg1 * CC + col) =
                make_float2(oacc[j][2] * inv1, oacc[j][3] * inv1);
    }
}

// ------------------------------- launch -------------------------------------
extern "C" void kernel_launch(void* const* d_in, const int* in_sizes, int n_in,
                              void* d_out, int out_size) {
    int sh = (in_sizes[5] == 1) ? 0 : -1;

    const float* xs  = (const float*)d_in[0];
    const float* ys  = (const float*)d_in[1];
    const int* rel   = (const int*)d_in[4];
    const float* qkv_w = (const float*)d_in[6 + sh];
    const float* ap_w  = (const float*)d_in[7 + sh];
    const float* ap_b  = (const float*)d_in[8 + sh];
    const float* q_w   = (const float*)d_in[9 + sh];
    const float* k_w   = (const float*)d_in[10 + sh];
    const float* v_w   = (const float*)d_in[11 + sh];
    const float* cp_w  = (const float*)d_in[12 + sh];
    const float* cp_b  = (const float*)d_in[13 + sh];
    const float* fc1_w = (const float*)d_in[14 + sh];
    const float* fc1_b = (const float*)d_in[15 + sh];
    const float* fc2_w = (const float*)d_in[16 + sh];
    const float* fc2_b = (const float*)d_in[17 + sh];
    const float* ln1w = (const float*)d_in[18 + sh];
    const float* ln1b = (const float*)d_in[19 + sh];
    const float* ln2w = (const float*)d_in[20 + sh];
    const float* ln2b = (const float*)d_in[21 + sh];
    const float* ln3w = (const float*)d_in[22 + sh];
    const float* ln3b = (const float*)d_in[23 + sh];
    const float* lnyw = (const float*)d_in[24 + sh];
    const float* lnyb = (const float*)d_in[25 + sh];
    float* out = (float*)d_out;

    float *x, *h, *yn, *qkv, *q, *k, *v, *o, *big, *big2;
    cudaGetSymbolAddress((void**)&x, g_x);
    cudaGetSymbolAddress((void**)&h, g_h);
    cudaGetSymbolAddress((void**)&yn, g_yn);
    cudaGetSymbolAddress((void**)&qkv, g_qkv);
    cudaGetSymbolAddress((void**)&q, g_q);
    cudaGetSymbolAddress((void**)&k, g_k);
    cudaGetSymbolAddress((void**)&v, g_v);
    cudaGetSymbolAddress((void**)&o, g_o);
    cudaGetSymbolAddress((void**)&big, g_big);
    cudaGetSymbolAddress((void**)&big2, g_big2);

    cudaFuncSetAttribute(gemm_tf32<0>, cudaFuncAttributeMaxDynamicSharedMemorySize, GEMM_SMEM);
    cudaFuncSetAttribute(gemm_tf32<1>, cudaFuncAttributeMaxDynamicSharedMemorySize, GEMM_SMEM);
    cudaFuncSetAttribute(gemm_tf32<2>, cudaFuncAttributeMaxDynamicSharedMemorySize, GEMM_SMEM);
    cudaFuncSetAttribute(gemm_tf32<3>, cudaFuncAttributeMaxDynamicSharedMemorySize, GEMM_SMEM);
    cudaFuncSetAttribute(attn_mma<false>, cudaFuncAttributeMaxDynamicSharedMemorySize, ATTN_SMEM);
    cudaFuncSetAttribute(attn_mma<true>,  cudaFuncAttributeMaxDynamicSharedMemorySize, ATTN_SMEM);

    copy_kernel<<<(T * CC + 255) / 256, 256>>>(xs, x, T * CC);

    // ---- self attention ----
    layernorm_kernel<<<T, 256>>>(x, ln1w, ln1b, h);
    gemm_tf32<0><<<dim3(3 * CC / 128, T / 128), 256, GEMM_SMEM>>>(h, qkv_w, nullptr, nullptr, qkv, T, 3 * CC, CC);
    attn_mma<false><<<dim3(4, PSELF), 256, ATTN_SMEM>>>(qkv, qkv, qkv, nullptr, o);
    gemm_tf32<2><<<dim3(CC / 128, T / 128), 256, GEMM_SMEM>>>(o, ap_w, ap_b, x, x, T, CC, CC);

    // ---- cross attention ----
    layernorm_kernel<<<T, 256>>>(x, ln2w, ln2b, h);
    layernorm_kernel<<<T, 256>>>(ys, lnyw, lnyb, yn);
    gemm_tf32<0><<<dim3(CC / 128, T / 128), 256, GEMM_SMEM>>>(h, q_w, nullptr, nullptr, q, T, CC, CC);
    gemm_tf32<0><<<dim3(CC / 128, T / 128), 256, GEMM_SMEM>>>(yn, k_w, nullptr, nullptr, k, T, CC, CC);
    gemm_tf32<0><<<dim3(CC / 128, T / 128), 256, GEMM_SMEM>>>(yn, v_w, nullptr, nullptr, v, T, CC, CC);
    attn_mma<true><<<dim3(4, PCROSS), 256, ATTN_SMEM>>>(q, k, v, rel, big);
    gemm_tf32<1><<<dim3(CC / 128, TT / 128), 256, GEMM_SMEM>>>(big, cp_w, cp_b, nullptr, big2, TT, CC, CC);
    merge_kernel<<<(T * CC + 255) / 256, 256>>>(big2, x);

    // ---- MLP ----
    layernorm_kernel<<<T, 256>>>(x, ln3w, ln3b, h);
    gemm_tf32<3><<<dim3(HID / 128, T / 128), 256, GEMM_SMEM>>>(h, fc1_w, fc1_b, nullptr, big2, T, HID, CC);
    gemm_tf32<2><<<dim3(CC / 128, T / 128), 256, GEMM_SMEM>>>(big2, fc2_w, fc2_b, x, out, T, CC, HID);
}

// round 6
// speedup vs baseline: 1.4458x; 1.4458x over previous
#include <cuda_runtime.h>
#include <cuda_bf16.h>
#include <math.h>
#include <stdint.h>

// ---------------------------------------------------------------------------
// MultiviewDecoderBlock (Vx=8, Vy=8, B=4, N=196, C=768, H=12, DH=64, M=4)
// cp.async 3-stage TF32 GEMMs + bf16 mma attention. Graph-capturable.
// ---------------------------------------------------------------------------

constexpr int VX = 8, BB = 4, NN = 196, CC = 768, HH = 12, DHH = 64, MV = 4;
constexpr int HID = 4 * CC;            // 3072
constexpr int VB = VX * BB;            // 32
constexpr int T  = VB * NN;            // 6272
constexpr int TT = VX * MV * BB * NN;  // 25088
constexpr int PSELF  = VB * HH;            // 384
constexpr int PCROSS = VX * MV * BB * HH;  // 1536
constexpr float ATTN_SCALE = 0.125f;

// -------------------------- device scratch ---------------------------------
__device__ float g_x  [T * CC];
__device__ float g_h  [T * CC];
__device__ float g_yn [T * CC];
__device__ float g_qkv[T * 3 * CC];
__device__ float g_q  [T * CC];
__device__ float g_k  [T * CC];
__device__ float g_v  [T * CC];
__device__ float g_o  [T * CC];
__device__ float g_big [TT * CC];
__device__ float g_big2[TT * CC];
__device__ float g_wr [9437184];   // tf32-rounded weights

// rounded-weight offsets
constexpr int WO_QKV = 0;                     // 3C*C = 1769472
constexpr int WO_AP  = 1769472;               // C*C
constexpr int WO_Q   = WO_AP  + CC * CC;
constexpr int WO_K   = WO_Q   + CC * CC;
constexpr int WO_V   = WO_K   + CC * CC;
constexpr int WO_CP  = WO_V   + CC * CC;
constexpr int WO_FC1 = WO_CP  + CC * CC;      // HID*C
constexpr int WO_FC2 = WO_FC1 + HID * CC;     // C*HID

extern __shared__ __align__(16) unsigned char dyn_smem[];

// ----------------------------- helpers -------------------------------------
__device__ __forceinline__ float tf32r(float f) {
    unsigned u; asm("cvt.rna.tf32.f32 %0, %1;" : "=r"(u) : "f"(f));
    return __uint_as_float(u);
}
__device__ __forceinline__ unsigned pkbf(float lo, float hi) {
    unsigned r;
    asm("cvt.rn.bf16x2.f32 %0, %1, %2;" : "=r"(r) : "f"(hi), "f"(lo));
    return r;
}
__device__ __forceinline__ void mma8(float* c, const unsigned* a, const unsigned* b) {
    asm volatile(
        "mma.sync.aligned.m16n8k8.row.col.f32.tf32.tf32.f32 "
        "{%0,%1,%2,%3},{%4,%5,%6,%7},{%8,%9},{%0,%1,%2,%3};\n"
        : "+f"(c[0]), "+f"(c[1]), "+f"(c[2]), "+f"(c[3])
        : "r"(a[0]), "r"(a[1]), "r"(a[2]), "r"(a[3]), "r"(b[0]), "r"(b[1]));
}
__device__ __forceinline__ void mma16(float* c, const unsigned* a, const unsigned* b) {
    asm volatile(
        "mma.sync.aligned.m16n8k16.row.col.f32.bf16.bf16.f32 "
        "{%0,%1,%2,%3},{%4,%5,%6,%7},{%8,%9},{%0,%1,%2,%3};\n"
        : "+f"(c[0]), "+f"(c[1]), "+f"(c[2]), "+f"(c[3])
        : "r"(a[0]), "r"(a[1]), "r"(a[2]), "r"(a[3]), "r"(b[0]), "r"(b[1]));
}
__device__ __forceinline__ void ldmx4t(unsigned* d, unsigned addr) {
    asm volatile("ldmatrix.sync.aligned.m8n8.x4.trans.shared.b16 {%0,%1,%2,%3}, [%4];"
                 : "=r"(d[0]), "=r"(d[1]), "=r"(d[2]), "=r"(d[3]) : "r"(addr));
}
__device__ __forceinline__ void cp16(unsigned d, const void* s) {
    asm volatile("cp.async.cg.shared.global [%0], [%1], 16;" :: "r"(d), "l"(s));
}

// ----------------------------- utility kernels ------------------------------
__global__ void copy_kernel(const float* __restrict__ src, float* __restrict__ dst, int n) {
    int i = blockIdx.x * blockDim.x + threadIdx.x;
    if (i < n) dst[i] = src[i];
}

__global__ void round_tf32_kernel(const float4* __restrict__ src, float4* __restrict__ dst, int n4) {
    int i = blockIdx.x * blockDim.x + threadIdx.x;
    if (i < n4) {
        float4 v = src[i];
        v.x = tf32r(v.x); v.y = tf32r(v.y); v.z = tf32r(v.z); v.w = tf32r(v.w);
        dst[i] = v;
    }
}

// LN with tf32-rounded output (all LN outputs feed GEMM A operands)
__global__ void layernorm_kernel(const float* __restrict__ in,
                                 const float* __restrict__ w,
                                 const float* __restrict__ b,
                                 float* __restrict__ out) {
    int row = blockIdx.x;
    const float* xr = in + (size_t)row * CC;
    float* orow = out + (size_t)row * CC;
    int tid = threadIdx.x;
    float v0 = xr[tid], v1 = xr[tid + 256], v2 = xr[tid + 512];
    float s  = v0 + v1 + v2;
    float sq = v0 * v0 + v1 * v1 + v2 * v2;
    #pragma unroll
    for (int off = 16; off; off >>= 1) {
        s  += __shfl_xor_sync(0xffffffffu, s, off);
        sq += __shfl_xor_sync(0xffffffffu, sq, off);
    }
    __shared__ float red[2][8];
    int warp = tid >> 5, lane = tid & 31;
    if (lane == 0) { red[0][warp] = s; red[1][warp] = sq; }
    __syncthreads();
    float ts = 0.f, tsq = 0.f;
    #pragma unroll
    for (int i = 0; i < 8; i++) { ts += red[0][i]; tsq += red[1][i]; }
    float mu = ts * (1.0f / CC);
    float var = tsq * (1.0f / CC) - mu * mu;
    float rstd = rsqrtf(var + 1e-5f);
    orow[tid]       = tf32r((v0 - mu) * rstd * w[tid]       + b[tid]);
    orow[tid + 256] = tf32r((v1 - mu) * rstd * w[tid + 256] + b[tid + 256]);
    orow[tid + 512] = tf32r((v2 - mu) * rstd * w[tid + 512] + b[tid + 512]);
}

__global__ void merge_kernel(const float* __restrict__ proj, float* __restrict__ x) {
    int idx = blockIdx.x * blockDim.x + threadIdx.x;
    if (idx >= T * CC) return;
    int c = idx % CC;
    int n = (idx / CC) % NN;
    int b = (idx / (CC * NN)) % BB;
    int v = idx / (CC * NN * BB);
    size_t base = ((((size_t)v * MV) * BB + b) * NN + n) * CC + c;
    size_t ms = (size_t)BB * NN * CC;
    float mx = proj[base];
    #pragma unroll
    for (int m = 1; m < MV; m++) mx = fmaxf(mx, proj[base + (size_t)m * ms]);
    x[idx] += mx;
}

// --------------------- TF32 GEMM, cp.async 3 stages -------------------------
// C = A @ B^T. A:(M,K) B:(N,K) row-major, pre-rounded to tf32 bit patterns.
// 128x128x32 tile, 256 thr, warp tile 64x32, smem swizzle g=(k>>2)^(row&7).
// EPI: 0=store, 1=+bias, 2=+bias+residual, 3=+bias+gelu(exact)+tf32round
constexpr int GSTAGES = 3;
constexpr int GEMM_SMEM = GSTAGES * 2 * 128 * 32 * 4;  // 98304

template<int EPI>
__global__ void __launch_bounds__(256) gemm_tf32(
    const float* __restrict__ A, const float* __restrict__ Bw,
    const float* __restrict__ bias, const float* __restrict__ res,
    float* __restrict__ C, int Mdim, int Ndim, int Kdim)
{
    const unsigned sbase = (unsigned)__cvta_generic_to_shared(dyn_smem);
    const int tid = threadIdx.x;
    const int lane = tid & 31, warp = tid >> 5;
    const int wm = (warp >> 2) * 64;
    const int wn = (warp & 3) * 32;
    const int bm = blockIdx.y * 128, bn = blockIdx.x * 128;
    const int lr = tid >> 3;
    const int lk = (tid & 7) * 4;
    const float* Ag = A  + (size_t)(bm + lr) * Kdim + lk;
    const float* Bg = Bw + (size_t)(bn + lr) * Kdim + lk;

    // per-thread swizzled smem byte addresses (stage 0)
    unsigned sa[4], sb[4];
    #pragma unroll
    for (int i = 0; i < 4; i++) {
        int row = lr + 32 * i;
        int g = (lk >> 2) ^ (row & 7);
        sa[i] = sbase + (unsigned)(row * 32 + g * 4) * 4u;
        sb[i] = sbase + (unsigned)(GSTAGES * 4096 + row * 32 + g * 4) * 4u;
    }

    float acc[4][4][4];
    #pragma unroll
    for (int i = 0; i < 4; i++)
        #pragma unroll
        for (int j = 0; j < 4; j++)
            #pragma unroll
            for (int t = 0; t < 4; t++) acc[i][j][t] = 0.f;

    const int nk = Kdim >> 5;
    // prologue: stages 0, 1
    #pragma unroll
    for (int s = 0; s < GSTAGES - 1; s++) {
        const float* a = Ag + s * 32;
        const float* b = Bg + s * 32;
        unsigned off = (unsigned)s * 16384u;
        #pragma unroll
        for (int i = 0; i < 4; i++) cp16(sa[i] + off, a + (size_t)32 * i * Kdim);
        #pragma unroll
        for (int i = 0; i < 4; i++) cp16(sb[i] + off, b + (size_t)32 * i * Kdim);
        asm volatile("cp.async.commit_group;");
    }

    const int r = lane >> 2, kq = lane & 3;
    #pragma unroll 1
    for (int kt = 0; kt < nk; kt++) {
        asm volatile("cp.async.wait_group 1;");
        __syncthreads();
        const int buf = kt % GSTAGES;
        const unsigned* Ab = (const unsigned*)dyn_smem + buf * 4096;
        const unsigned* Bb = (const unsigned*)dyn_smem + GSTAGES * 4096 + buf * 4096;
        #pragma unroll
        for (int ks = 0; ks < 4; ks++) {
            const int g0 = (((2 * ks)     ^ r) << 2) + kq;
            const int g1 = (((2 * ks + 1) ^ r) << 2) + kq;
            unsigned a[4][4], b[4][2];
            #pragma unroll
            for (int mf = 0; mf < 4; mf++) {
                const unsigned* p = Ab + (wm + mf * 16 + r) * 32;
                a[mf][0] = p[g0];
                a[mf][1] = p[8 * 32 + g0];
                a[mf][2] = p[g1];
                a[mf][3] = p[8 * 32 + g1];
            }
            #pragma unroll
            for (int nf = 0; nf < 4; nf++) {
                const unsigned* p = Bb + (wn + nf * 8 + r) * 32;
                b[nf][0] = p[g0];
                b[nf][1] = p[g1];
            }
            #pragma unroll
            for (int mf = 0; mf < 4; mf++)
                #pragma unroll
                for (int nf = 0; nf < 4; nf++)
                    mma8(acc[mf][nf], a[mf], b[nf]);
        }
        // prefetch stage kt + GSTAGES - 1
        if (kt + GSTAGES - 1 < nk) {
            int s = (kt + GSTAGES - 1) % GSTAGES;
            const float* a = Ag + (size_t)(kt + GSTAGES - 1) * 32;
            const float* b = Bg + (size_t)(kt + GSTAGES - 1) * 32;
            unsigned off = (unsigned)s * 16384u;
            #pragma unroll
            for (int i = 0; i < 4; i++) cp16(sa[i] + off, a + (size_t)32 * i * Kdim);
            #pragma unroll
            for (int i = 0; i < 4; i++) cp16(sb[i] + off, b + (size_t)32 * i * Kdim);
        }
        asm volatile("cp.async.commit_group;");
    }

    #pragma unroll
    for (int mf = 0; mf < 4; mf++) {
        #pragma unroll
        for (int nf = 0; nf < 4; nf++) {
            const int col = bn + wn + nf * 8 + (lane & 3) * 2;
            float bb0 = 0.f, bb1 = 0.f;
            if (EPI >= 1) { bb0 = bias[col]; bb1 = bias[col + 1]; }
            #pragma unroll
            for (int hh = 0; hh < 2; hh++) {
                const size_t row = (size_t)(bm + wm + mf * 16 + (lane >> 2) + hh * 8);
                float v0 = acc[mf][nf][hh * 2 + 0] + bb0;
                float v1 = acc[mf][nf][hh * 2 + 1] + bb1;
                if (EPI == 2) {
                    v0 += res[row * Ndim + col];
                    v1 += res[row * Ndim + col + 1];
                }
                if (EPI == 3) {
                    v0 = tf32r(0.5f * v0 * (1.0f + erff(v0 * 0.70710678118654752f)));
                    v1 = tf32r(0.5f * v1 * (1.0f + erff(v1 * 0.70710678118654752f)));
                }
                *(float2*)(C + row * Ndim + col) = make_float2(v0, v1);
            }
        }
    }
}

// ------------------------- bf16 mma attention -------------------------------
// One block: head-problem p, 64 query rows. 8 warps: wm in 0..3 (16 q-rows),
// wn in 0..1 (104-key half). Keys padded to 208. fp32 softmax in registers.
// smem (32-bit words): Q[64][36], K[208][36], V[208][36] (bf16 pairs,
// half-stride 72), P[64][108] overlapping Q+K, red floats at end.
constexpr int QWS = 36;
constexpr int PWS = 108;
constexpr int W_Q = 0;                 // 2304 words
constexpr int W_K = 2304;              // 7488 words
constexpr int W_V = 9792;              // 7488 words
constexpr int W_RED = 17280;           // 256 floats
constexpr int ATTN_SMEM = (W_RED + 256) * 4;  // 70144 bytes

template<bool CROSS>
__global__ void __launch_bounds__(256) attn_bf16(
    const float* __restrict__ Qsrc, const float* __restrict__ Ksrc,
    const float* __restrict__ Vsrc, const int* __restrict__ rel,
    float* __restrict__ Out)
{
    unsigned* W = (unsigned*)dyn_smem;
    unsigned* Qw = W + W_Q;
    unsigned* Kw = W + W_K;
    unsigned* Vw = W + W_V;
    unsigned* Pw = W;                        // overlap Q+K
    float* redmax = (float*)(W + W_RED);
    float* redsum = redmax + 128;
    const unsigned sbase = (unsigned)__cvta_generic_to_shared(dyn_smem);

    const int p = blockIdx.y;
    const int m0 = blockIdx.x * 64;
    const int tid = threadIdx.x;
    const int lane = tid & 31, warp = tid >> 5;
    const int wm = warp & 3, wn = warp >> 2;
    const int r = lane >> 2, q = lane & 3;

    const float *qp, *kp, *vp;
    float* op;
    int qrs, kvs;
    if (!CROSS) {
        int vb = p / HH, h2 = p % HH;
        const float* base = Qsrc + (size_t)vb * NN * 3 * CC;
        qp = base + h2 * DHH;
        kp = base + CC + h2 * DHH;
        vp = base + 2 * CC + h2 * DHH;
        qrs = 3 * CC; kvs = 3 * CC;
        op = Out + (size_t)vb * NN * CC + h2 * DHH;
    } else {
        int h2 = p % HH; int rr = p / HH;
        int b = rr % BB; int r2 = rr / BB;
        int mvi = r2 % MV; int v = r2 / MV;
        int vy = rel[v * MV + mvi];
        qp = Qsrc + ((size_t)(v * BB + b) * NN) * CC + h2 * DHH; qrs = CC;
        kp = Ksrc + ((size_t)(vy * BB + b) * NN) * CC + h2 * DHH;
        vp = Vsrc + ((size_t)(vy * BB + b) * NN) * CC + h2 * DHH; kvs = CC;
        op = Out + (size_t)rr * NN * CC + h2 * DHH;
    }

    // ---- load Q (64 x 64) as bf16 pairs ----
    #pragma unroll
    for (int it = 0; it < 4; it++) {
        int idx = tid + 256 * it;
        int row = idx >> 4, c4 = (idx & 15) * 4;
        float4 qv = make_float4(0.f, 0.f, 0.f, 0.f);
        if (m0 + row < NN) qv = *(const float4*)(qp + (size_t)(m0 + row) * qrs + c4);
        Qw[row * QWS + (c4 >> 1)]     = pkbf(qv.x, qv.y);
        Qw[row * QWS + (c4 >> 1) + 1] = pkbf(qv.z, qv.w);
    }
    // ---- load K, V (208 x 64), zero pad rows >= 196 ----
    #pragma unroll
    for (int it = 0; it < 13; it++) {
        int idx = tid + 256 * it;
        int row = idx >> 4, c4 = (idx & 15) * 4;
        float4 kv = make_float4(0.f, 0.f, 0.f, 0.f);
        float4 vv = make_float4(0.f, 0.f, 0.f, 0.f);
        if (row < NN) {
            kv = *(const float4*)(kp + (size_t)row * kvs + c4);
            vv = *(const float4*)(vp + (size_t)row * kvs + c4);
        }
        Kw[row * QWS + (c4 >> 1)]     = pkbf(kv.x, kv.y);
        Kw[row * QWS + (c4 >> 1) + 1] = pkbf(kv.z, kv.w);
        Vw[row * QWS + (c4 >> 1)]     = pkbf(vv.x, vv.y);
        Vw[row * QWS + (c4 >> 1) + 1] = pkbf(vv.z, vv.w);
    }
    __syncthreads();

    // ---- scores: warp computes m16 x n104, k = 64 (4 x k16) ----
    const int n0 = wn * 104;
    float sc[13][4];
    #pragma unroll
    for (int j = 0; j < 13; j++)
        #pragma unroll
        for (int t = 0; t < 4; t++) sc[j][t] = 0.f;

    #pragma unroll
    for (int kt = 0; kt < 4; kt++) {
        unsigned a[4];
        const unsigned* ap = Qw + (wm * 16 + r) * QWS + kt * 8 + q;
        a[0] = ap[0];
        a[1] = ap[8 * QWS];
        a[2] = ap[4];
        a[3] = ap[8 * QWS + 4];
        #pragma unroll
        for (int j = 0; j < 13; j++) {
            unsigned b[2];
            const unsigned* bp = Kw + (n0 + j * 8 + r) * QWS + kt * 8 + q;
            b[0] = bp[0];
            b[1] = bp[4];
            mma16(sc[j], a, b);
        }
    }

    // ---- scale + mask ----
    #pragma unroll
    for (int j = 0; j < 13; j++) {
        int cbase = n0 + j * 8 + 2 * q;
        #pragma unroll
        for (int t = 0; t < 4; t++) {
            int col = cbase + (t & 1);
            sc[j][t] = (col < NN) ? sc[j][t] * ATTN_SCALE : -1e30f;
        }
    }

    // ---- row max ----
    float mx0 = -1e30f, mx1 = -1e30f;
    #pragma unroll
    for (int j = 0; j < 13; j++) {
        mx0 = fmaxf(mx0, fmaxf(sc[j][0], sc[j][1]));
        mx1 = fmaxf(mx1, fmaxf(sc[j][2], sc[j][3]));
    }
    mx0 = fmaxf(mx0, __shfl_xor_sync(0xffffffffu, mx0, 1));
    mx0 = fmaxf(mx0, __shfl_xor_sync(0xffffffffu, mx0, 2));
    mx1 = fmaxf(mx1, __shfl_xor_sync(0xffffffffu, mx1, 1));
    mx1 = fmaxf(mx1, __shfl_xor_sync(0xffffffffu, mx1, 2));
    int rowl = wm * 16 + r;
    if (q == 0) {
        redmax[wn * 64 + rowl] = mx0;
        redmax[wn * 64 + rowl + 8] = mx1;
    }
    __syncthreads();   // also: all Q/K reads done -> P region reusable
    float fm0 = fmaxf(redmax[rowl], redmax[64 + rowl]);
    float fm1 = fmaxf(redmax[rowl + 8], redmax[64 + rowl + 8]);

    // ---- exp, row sum, write P as bf16 pairs ----
    float s0 = 0.f, s1 = 0.f;
    #pragma unroll
    for (int j = 0; j < 13; j++) {
        sc[j][0] = __expf(sc[j][0] - fm0);
        sc[j][1] = __expf(sc[j][1] - fm0);
        sc[j][2] = __expf(sc[j][2] - fm1);
        sc[j][3] = __expf(sc[j][3] - fm1);
        s0 += sc[j][0] + sc[j][1];
        s1 += sc[j][2] + sc[j][3];
    }
    s0 += __shfl_xor_sync(0xffffffffu, s0, 1);
    s0 += __shfl_xor_sync(0xffffffffu, s0, 2);
    s1 += __shfl_xor_sync(0xffffffffu, s1, 1);
    s1 += __shfl_xor_sync(0xffffffffu, s1, 2);
    if (q == 0) {
        redsum[wn * 64 + rowl] = s0;
        redsum[wn * 64 + rowl + 8] = s1;
    }
    #pragma unroll
    for (int j = 0; j < 13; j++) {
        int wbase = (n0 >> 1) + j * 4 + q;
        Pw[rowl * PWS + wbase]       = pkbf(sc[j][0], sc[j][1]);
        Pw[(rowl + 8) * PWS + wbase] = pkbf(sc[j][2], sc[j][3]);
    }
    __syncthreads();

    // ---- O = P @ V : warp computes m16 x n32 over k=208 (13 x k16) ----
    const int oc0 = wn * 32;
    float oacc[4][4];
    #pragma unroll
    for (int j = 0; j < 4; j++)
        #pragma unroll
        for (int t = 0; t < 4; t++) oacc[j][t] = 0.f;

    const int lrow = lane & 15;          // k row within 16
    const int lcol = (lane >> 4) * 8;    // n sub-tile
    #pragma unroll
    for (int kt = 0; kt < 13; kt++) {
        unsigned a[4];
        const unsigned* ap2 = Pw + rowl * PWS + kt * 8 + q;
        a[0] = ap2[0];
        a[1] = ap2[8 * PWS];
        a[2] = ap2[4];
        a[3] = ap2[8 * PWS + 4];
        #pragma unroll
        for (int jp = 0; jp < 2; jp++) {
            unsigned b4[4];
            unsigned addr = sbase + (unsigned)(W_V * 4) +
                (unsigned)((kt * 16 + lrow) * 72 + oc0 + jp * 16 + lcol) * 2u;
            ldmx4t(b4, addr);
            mma16(oacc[jp * 2 + 0], a, b4 + 0);
            mma16(oacc[jp * 2 + 1], a, b4 + 2);
        }
    }

    // ---- store O scaled by 1/rowsum, tf32-rounded (feeds GEMM A) ----
    float inv0 = 1.0f / (redsum[rowl] + redsum[64 + rowl]);
    float inv1 = 1.0f / (redsum[rowl + 8] + redsum[64 + rowl + 8]);
    int mg0 = m0 + rowl, mg1 = m0 + rowl + 8;
    #pragma unroll
    for (int j = 0; j < 4; j++) {
        int col = oc0 + j * 8 + 2 * q;
        if (mg0 < NN)
            *(float2*)(op + (size_t)mg0 * CC + col) =
                make_float2(tf32r(oacc[j][0] * inv0), tf32r(oacc[j][1] * inv0));
        if (mg1 < NN)
            *(float2*)(op + (size_t)mg1 * CC + col) =
                make_float2(tf32r(oacc[j][2] * inv1), tf32r(oacc[j][3] * inv1));
    }
}

// ------------------------------- launch -------------------------------------
static void round_w(const float* src, float* dst, int n) {
    int n4 = n / 4;
    round_tf32_kernel<<<(n4 + 255) / 256, 256>>>((const float4*)src, (float4*)dst, n4);
}

extern "C" void kernel_launch(void* const* d_in, const int* in_sizes, int n_in,
                              void* d_out, int out_size) {
    int sh = (in_sizes[5] == 1) ? 0 : -1;

    const float* xs  = (const float*)d_in[0];
    const float* ys  = (const float*)d_in[1];
    const int* rel   = (const int*)d_in[4];
    const float* qkv_w = (const float*)d_in[6 + sh];
    const float* ap_w  = (const float*)d_in[7 + sh];
    const float* ap_b  = (const float*)d_in[8 + sh];
    const float* q_w   = (const float*)d_in[9 + sh];
    const float* k_w   = (const float*)d_in[10 + sh];
    const float* v_w   = (const float*)d_in[11 + sh];
    const float* cp_w  = (const float*)d_in[12 + sh];
    const float* cp_b  = (const float*)d_in[13 + sh];
    const float* fc1_w = (const float*)d_in[14 + sh];
    const float* fc1_b = (const float*)d_in[15 + sh];
    const float* fc2_w = (const float*)d_in[16 + sh];
    const float* fc2_b = (const float*)d_in[17 + sh];
    const float* ln1w = (const float*)d_in[18 + sh];
    const float* ln1b = (const float*)d_in[19 + sh];
    const float* ln2w = (const float*)d_in[20 + sh];
    const float* ln2b = (const float*)d_in[21 + sh];
    const float* ln3w = (const float*)d_in[22 + sh];
    const float* ln3b = (const float*)d_in[23 + sh];
    const float* lnyw = (const float*)d_in[24 + sh];
    const float* lnyb = (const float*)d_in[25 + sh];
    float* out = (float*)d_out;

    float *x, *h, *yn, *qkv, *q, *k, *v, *o, *big, *big2, *wr;
    cudaGetSymbolAddress((void**)&x, g_x);
    cudaGetSymbolAddress((void**)&h, g_h);
    cudaGetSymbolAddress((void**)&yn, g_yn);
    cudaGetSymbolAddress((void**)&qkv, g_qkv);
    cudaGetSymbolAddress((void**)&q, g_q);
    cudaGetSymbolAddress((void**)&k, g_k);
    cudaGetSymbolAddress((void**)&v, g_v);
    cudaGetSymbolAddress((void**)&o, g_o);
    cudaGetSymbolAddress((void**)&big, g_big);
    cudaGetSymbolAddress((void**)&big2, g_big2);
    cudaGetSymbolAddress((void**)&wr, g_wr);

    cudaFuncSetAttribute(gemm_tf32<0>, cudaFuncAttributeMaxDynamicSharedMemorySize, GEMM_SMEM);
    cudaFuncSetAttribute(gemm_tf32<1>, cudaFuncAttributeMaxDynamicSharedMemorySize, GEMM_SMEM);
    cudaFuncSetAttribute(gemm_tf32<2>, cudaFuncAttributeMaxDynamicSharedMemorySize, GEMM_SMEM);
    cudaFuncSetAttribute(gemm_tf32<3>, cudaFuncAttributeMaxDynamicSharedMemorySize, GEMM_SMEM);
    cudaFuncSetAttribute(attn_bf16<false>, cudaFuncAttributeMaxDynamicSharedMemorySize, ATTN_SMEM);
    cudaFuncSetAttribute(attn_bf16<true>,  cudaFuncAttributeMaxDynamicSharedMemorySize, ATTN_SMEM);

    // tf32-round all GEMM weights into scratch
    round_w(qkv_w, wr + WO_QKV, 3 * CC * CC);
    round_w(ap_w,  wr + WO_AP,  CC * CC);
    round_w(q_w,   wr + WO_Q,   CC * CC);
    round_w(k_w,   wr + WO_K,   CC * CC);
    round_w(v_w,   wr + WO_V,   CC * CC);
    round_w(cp_w,  wr + WO_CP,  CC * CC);
    round_w(fc1_w, wr + WO_FC1, HID * CC);
    round_w(fc2_w, wr + WO_FC2, CC * HID);

    copy_kernel<<<(T * CC + 255) / 256, 256>>>(xs, x, T * CC);

    // ---- self attention ----
    layernorm_kernel<<<T, 256>>>(x, ln1w, ln1b, h);
    gemm_tf32<0><<<dim3(3 * CC / 128, T / 128), 256, GEMM_SMEM>>>(h, wr + WO_QKV, nullptr, nullptr, qkv, T, 3 * CC, CC);
    attn_bf16<false><<<dim3(4, PSELF), 256, ATTN_SMEM>>>(qkv, qkv, qkv, nullptr, o);
    gemm_tf32<2><<<dim3(CC / 128, T / 128), 256, GEMM_SMEM>>>(o, wr + WO_AP, ap_b, x, x, T, CC, CC);

    // ---- cross attention ----
    layernorm_kernel<<<T, 256>>>(x, ln2w, ln2b, h);
    layernorm_kernel<<<T, 256>>>(ys, lnyw, lnyb, yn);
    gemm_tf32<0><<<dim3(CC / 128, T / 128), 256, GEMM_SMEM>>>(h, wr + WO_Q, nullptr, nullptr, q, T, CC, CC);
    gemm_tf32<0><<<dim3(CC / 128, T / 128), 256, GEMM_SMEM>>>(yn, wr + WO_K, nullptr, nullptr, k, T, CC, CC);
    gemm_tf32<0><<<dim3(CC / 128, T / 128), 256, GEMM_SMEM>>>(yn, wr + WO_V, nullptr, nullptr, v, T, CC, CC);
    attn_bf16<true><<<dim3(4, PCROSS), 256, ATTN_SMEM>>>(q, k, v, rel, big);
    gemm_tf32<1><<<dim3(CC / 128, TT / 128), 256, GEMM_SMEM>>>(big, wr + WO_CP, cp_b, nullptr, big2, TT, CC, CC);
    merge_kernel<<<(T * CC + 255) / 256, 256>>>(big2, x);

    // ---- MLP ----
    layernorm_kernel<<<T, 256>>>(x, ln3w, ln3b, h);
    gemm_tf32<3><<<dim3(HID / 128, T / 128), 256, GEMM_SMEM>>>(h, wr + WO_FC1, fc1_b, nullptr, big2, T, HID, CC);
    gemm_tf32<2><<<dim3(CC / 128, T / 128), 256, GEMM_SMEM>>>(big2, wr + WO_FC2, fc2_b, x, out, T, CC, HID);
}